// round 11
// baseline (speedup 1.0000x reference)
#include <cuda_runtime.h>

#define NBR     4
#define RDIM    1024
#define FDIM    128
#define NDATA   100000
#define KTOT    4097
#define BATCHN  128
#define PER     (BATCHN*KTOT)          /* 524416 */
#define INV_T   14.285714285714286f    /* 1/0.07 */
#define C1      (0.04096f + 1e-7f)
#define LOGC0   (-3.1951593f)          /* ln(0.04096) */

typedef unsigned long long u64;
typedef longlong2 ll2;

// ---------------- device scratch (static allocs only) ----------------
__device__ float  g_hpart[8*4*BATCHN*FDIM];      // 2 MB  : k-split GEMM partials
__device__ float4 g_e4[4*BATCHN*(FDIM/4)];       // 256 KB: normalized embeddings
__device__ float  g_scr[16*PER];                 // 33.6 MB: unnormalized exp scores
__device__ float  g_zsum[16];                    // per-(i,j) exp sums

// packed f32x2 fma: d = a*b + d
__device__ __forceinline__ void fma2(u64 &d, u64 a, u64 b) {
    asm("fma.rn.f32x2 %0, %1, %2, %0;" : "+l"(d) : "l"(a), "l"(b));
}
__device__ __forceinline__ float lo_plus_hi(u64 v) {
    float a, b;
    asm("mov.b64 {%0, %1}, %2;" : "=f"(a), "=f"(b) : "l"(v));
    return a + b;
}

// ---------------- K0: zero accumulators + output ----------------
__global__ void k0_zero(float* out) {
    int t = threadIdx.x;
    if (t < 16) g_zsum[t] = 0.f;
    if (t == 0) out[0] = 0.f;
}

// ---------------- K1: partial GEMM  h_part[ks,r,b,d] ----------------
__global__ __launch_bounds__(256)
void k1_gemm(const float* __restrict__ e0, const float* __restrict__ e1,
             const float* __restrict__ e2, const float* __restrict__ e3,
             const float* __restrict__ W) {
    const int tile = blockIdx.x, ks = blockIdx.y, r = blockIdx.z;
    const float* emb = (r==0)?e0:(r==1)?e1:(r==2)?e2:e3;
    const int b0 = (tile & 3)*32, d0 = (tile>>2)*64;
    __shared__ float As[32][33];
    __shared__ float Bs[64][33];
    const int tid = threadIdx.x;
    const int tb = tid>>5, td = tid&31;
    float acc[4][2] = {};
    for (int kt = 0; kt < 4; kt++) {
        const int k0 = ks*128 + kt*32;
#pragma unroll
        for (int l = 0; l < 4; l++) {
            int lin = tid + l*256;
            As[lin>>5][lin&31] = emb[(b0+(lin>>5))*RDIM + k0 + (lin&31)];
        }
#pragma unroll
        for (int l = 0; l < 8; l++) {
            int lin = tid + l*256;
            Bs[lin>>5][lin&31] = W[r*FDIM*RDIM + (d0+(lin>>5))*RDIM + k0 + (lin&31)];
        }
        __syncthreads();
#pragma unroll
        for (int kk = 0; kk < 32; kk++) {
            float a0=As[tb*4+0][kk], a1=As[tb*4+1][kk], a2=As[tb*4+2][kk], a3=As[tb*4+3][kk];
            float w0=Bs[td*2+0][kk], w1=Bs[td*2+1][kk];
            acc[0][0]=fmaf(a0,w0,acc[0][0]); acc[0][1]=fmaf(a0,w1,acc[0][1]);
            acc[1][0]=fmaf(a1,w0,acc[1][0]); acc[1][1]=fmaf(a1,w1,acc[1][1]);
            acc[2][0]=fmaf(a2,w0,acc[2][0]); acc[2][1]=fmaf(a2,w1,acc[2][1]);
            acc[3][0]=fmaf(a3,w0,acc[3][0]); acc[3][1]=fmaf(a3,w1,acc[3][1]);
        }
        __syncthreads();
    }
#pragma unroll
    for (int bb=0; bb<4; bb++)
#pragma unroll
        for (int dd=0; dd<2; dd++)
            g_hpart[((ks*4+r)*BATCHN + b0+tb*4+bb)*FDIM + d0+td*2+dd] = acc[bb][dd];
}

// ---------------- K2: reduce partials + bias + L2-normalize ----------------
__global__ void k2_norm(const float* __restrict__ bias) {
    const int r = blockIdx.x, b = blockIdx.y, d = threadIdx.x;
    float s = bias[r*FDIM + d];
#pragma unroll
    for (int ks = 0; ks < 8; ks++)
        s += g_hpart[((ks*4+r)*BATCHN + b)*FDIM + d];
    float sq = s*s;
#pragma unroll
    for (int o = 16; o; o >>= 1) sq += __shfl_xor_sync(0xffffffffu, sq, o);
    __shared__ float ws[4];
    if ((d & 31) == 0) ws[d>>5] = sq;
    __syncthreads();
    const float tot = ws[0]+ws[1]+ws[2]+ws[3];
    ((float*)g_e4)[(r*BATCHN + b)*FDIM + d] = s * rsqrtf(tot);
}

// ---------------- K3 v6: R8 loop + eB/eC + nidx in smem -> 4 CTAs/SM ----------------
// grid (16 kc, 128 b, 4 j), 256 threads, j = blockIdx.z (clustered for L2).
// EXACT R8 loop schedule (in-place m prefetch mid-iteration, shfl tail with
// in-loop exp/STG/z). Register diet for occupancy: eA stays in 16 regs; eB/eC
// live in a 1KB smem table read per-chunk (LDS.128, 4-lane broadcast groups,
// conflict-free); per-thread row indices live in a per-warp smem table
// (1 LDS.32/iter, broadcast). launch_bounds(256,4) -> 32 warps/SM.
__global__ __launch_bounds__(256, 4)
void k3_scores(const float4* __restrict__ mem4, const int* __restrict__ cidx) {
    const int j  = blockIdx.z;
    const int i0 = (j==0) ? 1 : 0;
    const int i1 = (j<=1) ? 2 : 1;
    const int i2 = (j==3) ? 2 : 3;
    const int kcb = blockIdx.x;
    const int b   = blockIdx.y;
    const int tid = threadIdx.x;
    const int lane = tid & 31, w = tid >> 5;
    const int seg = lane & 7, rg = lane >> 3;

    __shared__ float4 esm[2][32];    // [0]=e[i1] (B), [1]=e[i2] (C)
    __shared__ int    sidx[8][32];   // per-warp row indices, slot s=(it*4+rg)

    const int cbase = b*KTOT;

    // ---- init smem: eB/eC table + this block's 256 row indices ----
    if (tid < 64) {
        const int br = tid >> 5, c = tid & 31;
        const int ii = br ? i2 : i1;
        esm[br][c] = g_e4[(ii*BATCHN + b)*32 + c];
    }
    sidx[w][lane] = cidx[cbase + 1 + kcb*256 + w*4 + (lane>>2)*32 + (lane&3)];

    // ---- eA into registers ----
    const ll2* e2p = (const ll2*)g_e4;
    u64 eA[8];
#pragma unroll
    for (int ii = 0; ii < 4; ii++) {
        ll2 vA = e2p[(i0*BATCHN + b)*32 + seg + 8*ii];
        eA[2*ii] = (u64)vA.x; eA[2*ii+1] = (u64)vA.y;
    }

    const int  kbase = 1 + kcb*256 + w*4 + rg;
    const int  sb0 = (i0*4+j)*PER + cbase;
    const int  sb1 = (i1*4+j)*PER + cbase;
    const int  sb2 = (i2*4+j)*PER + cbase;
    const ll2* base = (const ll2*)mem4 + (long)j*NDATA*32 + seg;
    const ll2* esll = (const ll2*)esm;      // B at [c], C at [32+c]

    __syncthreads();

    float zA = 0.f, zB = 0.f, zC = 0.f;

    // ---- main loop: R8 schedule, e-operands from smem ----
    {
        const ll2* rp = base + (long)sidx[w][rg]*32;   // row of it=0 (slot rg)
        ll2 m0 = rp[0], m1 = rp[8], m2 = rp[16], m3 = rp[24];

#pragma unroll
        for (int it = 0; it < 8; it++) {
            const int n_next = sidx[w][((it+1)&7)*4 + rg];
            const ll2* rq = base + (long)n_next*32;
            u64 a0=0,a1=0,b0_=0,b1_=0,c0=0,c1=0;
            // chunk 0
            { ll2 eb = esll[seg],    ec = esll[32+seg];
              fma2(a0,(u64)m0.x,eA[0]);      fma2(a1,(u64)m0.y,eA[1]);
              fma2(b0_,(u64)m0.x,(u64)eb.x); fma2(b1_,(u64)m0.y,(u64)eb.y);
              fma2(c0,(u64)m0.x,(u64)ec.x);  fma2(c1,(u64)m0.y,(u64)ec.y); }
            if (it < 7) m0 = rq[0];
            // chunk 1
            { ll2 eb = esll[8+seg],  ec = esll[40+seg];
              fma2(a0,(u64)m1.x,eA[2]);      fma2(a1,(u64)m1.y,eA[3]);
              fma2(b0_,(u64)m1.x,(u64)eb.x); fma2(b1_,(u64)m1.y,(u64)eb.y);
              fma2(c0,(u64)m1.x,(u64)ec.x);  fma2(c1,(u64)m1.y,(u64)ec.y); }
            if (it < 7) m1 = rq[8];
            // chunk 2
            { ll2 eb = esll[16+seg], ec = esll[48+seg];
              fma2(a0,(u64)m2.x,eA[4]);      fma2(a1,(u64)m2.y,eA[5]);
              fma2(b0_,(u64)m2.x,(u64)eb.x); fma2(b1_,(u64)m2.y,(u64)eb.y);
              fma2(c0,(u64)m2.x,(u64)ec.x);  fma2(c1,(u64)m2.y,(u64)ec.y); }
            if (it < 7) m2 = rq[16];
            // chunk 3
            { ll2 eb = esll[24+seg], ec = esll[56+seg];
              fma2(a0,(u64)m3.x,eA[6]);      fma2(a1,(u64)m3.y,eA[7]);
              fma2(b0_,(u64)m3.x,(u64)eb.x); fma2(b1_,(u64)m3.y,(u64)eb.y);
              fma2(c0,(u64)m3.x,(u64)ec.x);  fma2(c1,(u64)m3.y,(u64)ec.y); }
            if (it < 7) m3 = rq[24];
            // reduction tail (overlaps in-flight loads) — R8 exact
            float dA = lo_plus_hi(a0) + lo_plus_hi(a1);
            float dB = lo_plus_hi(b0_) + lo_plus_hi(b1_);
            float dC = lo_plus_hi(c0) + lo_plus_hi(c1);
#pragma unroll
            for (int o = 1; o < 8; o <<= 1) {
                dA += __shfl_xor_sync(0xffffffffu, dA, o);
                dB += __shfl_xor_sync(0xffffffffu, dB, o);
                dC += __shfl_xor_sync(0xffffffffu, dC, o);
            }
            if (seg == 0) {
                const int k = kbase + it*32;
                float v;
                v = __expf(dA*INV_T); g_scr[sb0+k] = v; zA += v;
                v = __expf(dB*INV_T); g_scr[sb1+k] = v; zB += v;
                v = __expf(dC*INV_T); g_scr[sb2+k] = v; zC += v;
            }
        }
    }

    // ---- positive sample (k==0), handled once per (b,j) by the kcb==0 block ----
    if (kcb == 0 && tid < 32) {
        const int n = cidx[cbase];
        const float4 m = (mem4 + ((long)j*NDATA + n)*32)[lane];
        const float4 fA = g_e4[(i0*BATCHN + b)*32 + lane];
        const float4 fB = g_e4[(i1*BATCHN + b)*32 + lane];
        const float4 fC = g_e4[(i2*BATCHN + b)*32 + lane];
        float pA = m.x*fA.x + m.y*fA.y + m.z*fA.z + m.w*fA.w;
        float pB = m.x*fB.x + m.y*fB.y + m.z*fB.z + m.w*fB.w;
        float pC = m.x*fC.x + m.y*fC.y + m.z*fC.z + m.w*fC.w;
#pragma unroll
        for (int o = 16; o; o >>= 1) {
            pA += __shfl_down_sync(0xffffffffu, pA, o);
            pB += __shfl_down_sync(0xffffffffu, pB, o);
            pC += __shfl_down_sync(0xffffffffu, pC, o);
        }
        if (tid == 0) {
            float v;
            v = __expf(pA*INV_T); g_scr[sb0] = v; atomicAdd(&g_zsum[i0*4+j], v);
            v = __expf(pB*INV_T); g_scr[sb1] = v; atomicAdd(&g_zsum[i1*4+j], v);
            v = __expf(pC*INV_T); g_scr[sb2] = v; atomicAdd(&g_zsum[i2*4+j], v);
        }
    }

    // ---- block-reduce Z partials ----
    __shared__ float ws[3][8];
    float zz[3] = {zA, zB, zC};
#pragma unroll
    for (int t2 = 0; t2 < 3; t2++) {
        float v = zz[t2];
#pragma unroll
        for (int o = 16; o; o >>= 1) v += __shfl_down_sync(0xffffffffu, v, o);
        if (lane == 0) ws[t2][w] = v;
    }
    __syncthreads();
    if (tid == 0) {
        const int ii[3] = {i0, i1, i2};
#pragma unroll
        for (int t2 = 0; t2 < 3; t2++) {
            float s = 0.f;
#pragma unroll
            for (int wi = 0; wi < 8; wi++) s += ws[t2][wi];
            atomicAdd(&g_zsum[ii[t2]*4+j], s);
        }
    }
}

// ---------------- K4: normalize by Z, log terms, final reduction ----------------
__global__ __launch_bounds__(256)
void k4_loss(float* out) {
    const int p12 = blockIdx.y;
    const int i = p12/3, jo = p12 - i*3;
    const int j = jo + (jo >= i ? 1 : 0);
    const int pair = i*4 + j;
    __shared__ float sInvZ;
    if (threadIdx.x == 0) {
        float Z = g_zsum[pair] * ((float)NDATA / (float)PER);
        sInvZ = 1.0f / Z;
    }
    __syncthreads();
    const float invZ = sInvZ;
    const int base = pair*PER;
    float lsum = 0.f;
    for (int idx = blockIdx.x*blockDim.x + threadIdx.x; idx < PER; idx += gridDim.x*blockDim.x) {
        float v = g_scr[base+idx]*invZ;
        lsum += LOGC0 - __logf(v + C1);
    }
    if (blockIdx.x == 0 && threadIdx.x < BATCHN) {
        float v = g_scr[base + threadIdx.x*KTOT]*invZ;
        lsum += __logf(v) - LOGC0;
    }
    __shared__ float red[8];
    float v = lsum;
#pragma unroll
    for (int o = 16; o; o >>= 1) v += __shfl_down_sync(0xffffffffu, v, o);
    if ((threadIdx.x & 31) == 0) red[threadIdx.x>>5] = v;
    __syncthreads();
    if (threadIdx.x == 0) {
        float s = 0.f;
#pragma unroll
        for (int w = 0; w < 8; w++) s += red[w];
        atomicAdd(out, s * (-1.0f/(float)BATCHN));
    }
}

// ---------------- launch ----------------
extern "C" void kernel_launch(void* const* d_in, const int* in_sizes, int n_in,
                              void* d_out, int out_size) {
    const float* e0   = (const float*)d_in[0];
    const float* e1   = (const float*)d_in[1];
    const float* e2   = (const float*)d_in[2];
    const float* e3   = (const float*)d_in[3];
    const float* W    = (const float*)d_in[4];
    const float* bias = (const float*)d_in[5];
    const float4* mem = (const float4*)d_in[6];
    const int* cidx   = (const int*)d_in[8];
    float* out        = (float*)d_out;

    k0_zero<<<1, 32>>>(out);
    k1_gemm<<<dim3(8,8,4), 256>>>(e0, e1, e2, e3, W);
    k2_norm<<<dim3(4,128), 128>>>(bias);
    k3_scores<<<dim3(16,128,4), 256>>>(mem, cidx);   // j = blockIdx.z (clustered)
    k4_loss<<<dim3(128,12), 256>>>(out);
}

// round 14
// speedup vs baseline: 1.4154x; 1.4154x over previous
#include <cuda_runtime.h>

#define NBR     4
#define RDIM    1024
#define FDIM    128
#define NDATA   100000
#define KTOT    4097
#define BATCHN  128
#define PER     (BATCHN*KTOT)          /* 524416 */
#define INV_T   14.285714285714286f    /* 1/0.07 */
#define C1      (0.04096f + 1e-7f)
#define LOGC0   (-3.1951593f)          /* ln(0.04096) */

typedef unsigned long long u64;
typedef longlong2 ll2;

// ---------------- device scratch (static allocs only) ----------------
__device__ float  g_hpart[16*4*BATCHN*FDIM];     // 4 MB  : k-split GEMM partials
__device__ float4 g_e4[4*BATCHN*(FDIM/4)];       // 256 KB: normalized embeddings
__device__ float  g_scr[16*PER];                 // 33.6 MB: unnormalized exp scores
__device__ float  g_zsum[16];                    // per-(i,j) exp sums

// packed f32x2 fma: d = a*b + d
__device__ __forceinline__ void fma2(u64 &d, u64 a, u64 b) {
    asm("fma.rn.f32x2 %0, %1, %2, %0;" : "+l"(d) : "l"(a), "l"(b));
}
__device__ __forceinline__ float lo_plus_hi(u64 v) {
    float a, b;
    asm("mov.b64 {%0, %1}, %2;" : "=f"(a), "=f"(b) : "l"(v));
    return a + b;
}

// ---------------- K0: zero accumulators + output ----------------
__global__ void k0_zero(float* out) {
    int t = threadIdx.x;
    if (t < 16) g_zsum[t] = 0.f;
    if (t == 0) out[0] = 0.f;
}

// ---------------- K1: partial GEMM  h_part[ks,r,b,d] (16 k-splits) ----------------
__global__ __launch_bounds__(256)
void k1_gemm(const float* __restrict__ e0, const float* __restrict__ e1,
             const float* __restrict__ e2, const float* __restrict__ e3,
             const float* __restrict__ W) {
    const int tile = blockIdx.x, ks = blockIdx.y, r = blockIdx.z;
    const float* emb = (r==0)?e0:(r==1)?e1:(r==2)?e2:e3;
    const int b0 = (tile & 3)*32, d0 = (tile>>2)*64;
    __shared__ float As[32][33];
    __shared__ float Bs[64][33];
    const int tid = threadIdx.x;
    const int tb = tid>>5, td = tid&31;
    float acc[4][2] = {};
    for (int kt = 0; kt < 2; kt++) {
        const int k0 = ks*64 + kt*32;
#pragma unroll
        for (int l = 0; l < 4; l++) {
            int lin = tid + l*256;
            As[lin>>5][lin&31] = emb[(b0+(lin>>5))*RDIM + k0 + (lin&31)];
        }
#pragma unroll
        for (int l = 0; l < 8; l++) {
            int lin = tid + l*256;
            Bs[lin>>5][lin&31] = W[r*FDIM*RDIM + (d0+(lin>>5))*RDIM + k0 + (lin&31)];
        }
        __syncthreads();
#pragma unroll
        for (int kk = 0; kk < 32; kk++) {
            float a0=As[tb*4+0][kk], a1=As[tb*4+1][kk], a2=As[tb*4+2][kk], a3=As[tb*4+3][kk];
            float w0=Bs[td*2+0][kk], w1=Bs[td*2+1][kk];
            acc[0][0]=fmaf(a0,w0,acc[0][0]); acc[0][1]=fmaf(a0,w1,acc[0][1]);
            acc[1][0]=fmaf(a1,w0,acc[1][0]); acc[1][1]=fmaf(a1,w1,acc[1][1]);
            acc[2][0]=fmaf(a2,w0,acc[2][0]); acc[2][1]=fmaf(a2,w1,acc[2][1]);
            acc[3][0]=fmaf(a3,w0,acc[3][0]); acc[3][1]=fmaf(a3,w1,acc[3][1]);
        }
        __syncthreads();
    }
#pragma unroll
    for (int bb=0; bb<4; bb++)
#pragma unroll
        for (int dd=0; dd<2; dd++)
            g_hpart[((ks*4+r)*BATCHN + b0+tb*4+bb)*FDIM + d0+td*2+dd] = acc[bb][dd];
}

// ---------------- K2: reduce partials + bias + L2-normalize ----------------
__global__ void k2_norm(const float* __restrict__ bias) {
    const int r = blockIdx.x, b = blockIdx.y, d = threadIdx.x;
    float s = bias[r*FDIM + d];
#pragma unroll
    for (int ks = 0; ks < 16; ks++)
        s += g_hpart[((ks*4+r)*BATCHN + b)*FDIM + d];
    float sq = s*s;
#pragma unroll
    for (int o = 16; o; o >>= 1) sq += __shfl_xor_sync(0xffffffffu, sq, o);
    __shared__ float ws[4];
    if ((d & 31) == 0) ws[d>>5] = sq;
    __syncthreads();
    const float tot = ws[0]+ws[1]+ws[2]+ws[3];
    ((float*)g_e4)[(r*BATCHN + b)*FDIM + d] = s * rsqrtf(tot);
}

// ---------------- K3 v7: R8 loop + merged 3-value reduction tail ----------------
// grid (16 kc, 128 b, 4 j), 256 threads, j = blockIdx.z (clustered for L2).
// EXACT R8 main loop (register e-vectors, in-place m prefetch mid-iteration).
// Tail change only: per-value shfl levels 1,2 give quad sums; ONE shared
// level-4 shuffle on the sel=seg&3-selected value finishes all three dots, so
// lanes seg=0/1/2 of each 8-lane group carry dA/dB/dC. exp/store/z then run as
// single instructions at 12 active lanes (was 3x at 4 lanes). SHFL 9->7/iter.
__global__ __launch_bounds__(256, 3)
void k3_scores(const float4* __restrict__ mem4, const int* __restrict__ cidx) {
    const int j  = blockIdx.z;
    const int i0 = (j==0) ? 1 : 0;
    const int i1 = (j<=1) ? 2 : 1;
    const int i2 = (j==3) ? 2 : 3;
    const int kcb = blockIdx.x;
    const int b   = blockIdx.y;
    const int tid = threadIdx.x;
    const int lane = tid & 31, w = tid >> 5;
    const int seg = lane & 7, rg = lane >> 3;
    const int sel = seg & 3;

    // ---- e-vectors into registers (one-time) ----
    const ll2* e2p = (const ll2*)g_e4;
    u64 eA[8], eB[8], eC[8];
#pragma unroll
    for (int ii = 0; ii < 4; ii++) {
        ll2 vA = e2p[(i0*BATCHN + b)*32 + seg + 8*ii];
        ll2 vB = e2p[(i1*BATCHN + b)*32 + seg + 8*ii];
        ll2 vC = e2p[(i2*BATCHN + b)*32 + seg + 8*ii];
        eA[2*ii] = (u64)vA.x; eA[2*ii+1] = (u64)vA.y;
        eB[2*ii] = (u64)vB.x; eB[2*ii+1] = (u64)vB.y;
        eC[2*ii] = (u64)vC.x; eC[2*ii+1] = (u64)vC.y;
    }

    const int  cbase = b*KTOT;
    const int  sb0 = (i0*4+j)*PER + cbase;
    const int  sb1 = (i1*4+j)*PER + cbase;
    const int  sb2 = (i2*4+j)*PER + cbase;
    const int  sbsel = (sel==0) ? sb0 : (sel==1) ? sb1 : sb2;   // lane's store base
    const ll2* base = (const ll2*)mem4 + (long)j*NDATA*32 + seg;

    // ---- prefetch this thread's 8 row indices ----
    const int kbase = 1 + kcb*256 + w*4 + rg;
    int nidx[8];
#pragma unroll
    for (int it = 0; it < 8; it++) nidx[it] = cidx[cbase + kbase + it*32];

    float z = 0.f;    // per-lane: branch 'sel' partial Z (seg<3 lanes only)

    // ---- main loop: R8 schedule ----
    {
        const ll2* rp = base + (long)nidx[0]*32;
        ll2 m0 = rp[0], m1 = rp[8], m2 = rp[16], m3 = rp[24];

#pragma unroll
        for (int it = 0; it < 8; it++) {
            u64 a0=0,a1=0,b0_=0,b1_=0,c0=0,c1=0;
            // chunks 0,1
            fma2(a0,(u64)m0.x,eA[0]); fma2(a1,(u64)m0.y,eA[1]);
            fma2(b0_,(u64)m0.x,eB[0]); fma2(b1_,(u64)m0.y,eB[1]);
            fma2(c0,(u64)m0.x,eC[0]); fma2(c1,(u64)m0.y,eC[1]);
            fma2(a0,(u64)m1.x,eA[2]); fma2(a1,(u64)m1.y,eA[3]);
            fma2(b0_,(u64)m1.x,eB[2]); fma2(b1_,(u64)m1.y,eB[3]);
            fma2(c0,(u64)m1.x,eC[2]); fma2(c1,(u64)m1.y,eC[3]);
            // prefetch next row, first half (in-place)
            const ll2* rq = base + (long)nidx[(it+1) & 7]*32;
            if (it < 7) { m0 = rq[0]; m1 = rq[8]; }
            // chunks 2,3
            fma2(a0,(u64)m2.x,eA[4]); fma2(a1,(u64)m2.y,eA[5]);
            fma2(b0_,(u64)m2.x,eB[4]); fma2(b1_,(u64)m2.y,eB[5]);
            fma2(c0,(u64)m2.x,eC[4]); fma2(c1,(u64)m2.y,eC[5]);
            fma2(a0,(u64)m3.x,eA[6]); fma2(a1,(u64)m3.y,eA[7]);
            fma2(b0_,(u64)m3.x,eB[6]); fma2(b1_,(u64)m3.y,eB[7]);
            fma2(c0,(u64)m3.x,eC[6]); fma2(c1,(u64)m3.y,eC[7]);
            // prefetch next row, second half (in-place)
            if (it < 7) { m2 = rq[16]; m3 = rq[24]; }
            // merged reduction tail
            float dA = lo_plus_hi(a0) + lo_plus_hi(a1);
            float dB = lo_plus_hi(b0_) + lo_plus_hi(b1_);
            float dC = lo_plus_hi(c0) + lo_plus_hi(c1);
            dA += __shfl_xor_sync(0xffffffffu, dA, 1);
            dB += __shfl_xor_sync(0xffffffffu, dB, 1);
            dC += __shfl_xor_sync(0xffffffffu, dC, 1);
            dA += __shfl_xor_sync(0xffffffffu, dA, 2);
            dB += __shfl_xor_sync(0xffffffffu, dB, 2);
            dC += __shfl_xor_sync(0xffffffffu, dC, 2);
            float v = (sel==0) ? dA : (sel==1) ? dB : dC;   // quad sum of lane's branch
            v += __shfl_xor_sync(0xffffffffu, v, 4);        // full 8-seg sum
            if (seg < 3) {
                float ex = __expf(v*INV_T);
                g_scr[sbsel + kbase + it*32] = ex;
                z += ex;
            }
        }
    }

    // ---- positive sample (k==0), handled once per (b,j) by the kcb==0 block ----
    if (kcb == 0 && tid < 32) {
        const int n = cidx[cbase];
        const float4 m = (mem4 + ((long)j*NDATA + n)*32)[lane];
        const float4 fA = g_e4[(i0*BATCHN + b)*32 + lane];
        const float4 fB = g_e4[(i1*BATCHN + b)*32 + lane];
        const float4 fC = g_e4[(i2*BATCHN + b)*32 + lane];
        float pA = m.x*fA.x + m.y*fA.y + m.z*fA.z + m.w*fA.w;
        float pB = m.x*fB.x + m.y*fB.y + m.z*fB.z + m.w*fB.w;
        float pC = m.x*fC.x + m.y*fC.y + m.z*fC.z + m.w*fC.w;
#pragma unroll
        for (int o = 16; o; o >>= 1) {
            pA += __shfl_down_sync(0xffffffffu, pA, o);
            pB += __shfl_down_sync(0xffffffffu, pB, o);
            pC += __shfl_down_sync(0xffffffffu, pC, o);
        }
        if (tid == 0) {
            float v;
            v = __expf(pA*INV_T); g_scr[sb0] = v; atomicAdd(&g_zsum[i0*4+j], v);
            v = __expf(pB*INV_T); g_scr[sb1] = v; atomicAdd(&g_zsum[i1*4+j], v);
            v = __expf(pC*INV_T); g_scr[sb2] = v; atomicAdd(&g_zsum[i2*4+j], v);
        }
    }

    // ---- Z reduction: lane seg==s carries branch s; fold rg groups, then block ----
    __shared__ float ws[3][8];
    {
        float v = z;
        v += __shfl_down_sync(0xffffffffu, v, 16);
        v += __shfl_down_sync(0xffffffffu, v, 8);
        if (lane < 3) ws[lane][w] = v;     // lane 0/1/2 = warp zA/zB/zC
    }
    __syncthreads();
    if (tid == 0) {
        const int ii[3] = {i0, i1, i2};
#pragma unroll
        for (int t2 = 0; t2 < 3; t2++) {
            float s = 0.f;
#pragma unroll
            for (int wi = 0; wi < 8; wi++) s += ws[t2][wi];
            atomicAdd(&g_zsum[ii[t2]*4+j], s);
        }
    }
}

// ---------------- K4: normalize by Z, log terms, final reduction ----------------
__global__ __launch_bounds__(256)
void k4_loss(float* out) {
    const int p12 = blockIdx.y;
    const int i = p12/3, jo = p12 - i*3;
    const int j = jo + (jo >= i ? 1 : 0);
    const int pair = i*4 + j;
    __shared__ float sInvZ;
    if (threadIdx.x == 0) {
        float Z = g_zsum[pair] * ((float)NDATA / (float)PER);
        sInvZ = 1.0f / Z;
    }
    __syncthreads();
    const float invZ = sInvZ;
    const int base = pair*PER;
    float lsum = 0.f;
    for (int idx = blockIdx.x*blockDim.x + threadIdx.x; idx < PER; idx += gridDim.x*blockDim.x) {
        float v = g_scr[base+idx]*invZ;
        lsum += LOGC0 - __logf(v + C1);
    }
    if (blockIdx.x == 0 && threadIdx.x < BATCHN) {
        float v = g_scr[base + threadIdx.x*KTOT]*invZ;
        lsum += __logf(v) - LOGC0;
    }
    __shared__ float red[8];
    float v = lsum;
#pragma unroll
    for (int o = 16; o; o >>= 1) v += __shfl_down_sync(0xffffffffu, v, o);
    if ((threadIdx.x & 31) == 0) red[threadIdx.x>>5] = v;
    __syncthreads();
    if (threadIdx.x == 0) {
        float s = 0.f;
#pragma unroll
        for (int w = 0; w < 8; w++) s += red[w];
        atomicAdd(out, s * (-1.0f/(float)BATCHN));
    }
}

// ---------------- launch ----------------
extern "C" void kernel_launch(void* const* d_in, const int* in_sizes, int n_in,
                              void* d_out, int out_size) {
    const float* e0   = (const float*)d_in[0];
    const float* e1   = (const float*)d_in[1];
    const float* e2   = (const float*)d_in[2];
    const float* e3   = (const float*)d_in[3];
    const float* W    = (const float*)d_in[4];
    const float* bias = (const float*)d_in[5];
    const float4* mem = (const float4*)d_in[6];
    const int* cidx   = (const int*)d_in[8];
    float* out        = (float*)d_out;

    k0_zero<<<1, 32>>>(out);
    k1_gemm<<<dim3(8,16,4), 256>>>(e0, e1, e2, e3, W);
    k2_norm<<<dim3(4,128), 128>>>(bias);
    k3_scores<<<dim3(16,128,4), 256>>>(mem, cidx);   // j = blockIdx.z (clustered)
    k4_loss<<<dim3(128,12), 256>>>(out);
}